// round 4
// baseline (speedup 1.0000x reference)
#include <cuda_runtime.h>
#include <cstdint>

#define N_NODES 50000
#define N_EDGES 1600000
#define IN_DIM 64
#define HD 64
#define NUM_HEADS 4
#define OUT_DIM 16

// ---------------- device scratch ----------------
__device__ float g_Q[N_NODES * HD];
__device__ float g_K[N_NODES * HD];
__device__ float g_V[N_NODES * HD];
__device__ float g_Z[N_NODES * NUM_HEADS];

// ---------------- helpers ----------------
__device__ __forceinline__ void red_add_v4(float* p, float a, float b, float c, float d) {
    asm volatile("red.global.add.v4.f32 [%0], {%1,%2,%3,%4};"
                 :: "l"(p), "f"(a), "f"(b), "f"(c), "f"(d) : "memory");
}
__device__ __forceinline__ void fma2(uint64_t& d, uint64_t a, uint64_t b) {
    asm("fma.rn.f32x2 %0, %1, %2, %0;" : "+l"(d) : "l"(a), "l"(b));
}
__device__ __forceinline__ float hsum2(uint64_t v) {
    float2 f = *reinterpret_cast<float2*>(&v);
    return f.x + f.y;
}

// packed/permuted weights: w2[cp*64 + (d&7)*8 + (d>>3)] = (W[2cp][d], W[2cp+1][d])
__device__ __forceinline__ void build_w2(uint64_t* __restrict__ w2,
                                         const float* __restrict__ W, int tid) {
    for (int idx = tid; idx < 2048; idx += 128) {
        int cp = idx >> 6, d = idx & 63;
        float2 p = make_float2(W[(2 * cp) * 64 + d], W[(2 * cp + 1) * 64 + d]);
        w2[cp * 64 + (d & 7) * 8 + (d >> 3)] = *reinterpret_cast<uint64_t*>(&p);
    }
}

// ---------------- zero init ----------------
__global__ void zero_kernel(float* __restrict__ out) {
    int i = blockIdx.x * blockDim.x + threadIdx.x;
    if (i < N_NODES * HD) out[i] = 0.0f;
    if (i < N_NODES * NUM_HEADS) g_Z[i] = 0.0f;
}

// ---------------- node projections (unchanged from R3, known good) ----------------
#define PROJ_SMEM_FLOATS (128 * 65 + 64 * 64 + 64)
__global__ __launch_bounds__(128)
void proj_kernel(const float* __restrict__ x,
                 const float* __restrict__ WQ, const float* __restrict__ bQ,
                 const float* __restrict__ WK, const float* __restrict__ bK,
                 const float* __restrict__ WV, const float* __restrict__ bV) {
    const float* W; const float* b; float* out;
    if (blockIdx.y == 0)      { W = WQ; b = bQ; out = g_Q; }
    else if (blockIdx.y == 1) { W = WK; b = bK; out = g_K; }
    else                      { W = WV; b = bV; out = g_V; }

    extern __shared__ float sm[];
    float* x_s = sm;
    float* w_s = sm + 128 * 65;
    float* b_s = w_s + 64 * 64;

    const int tid = threadIdx.x;
    const int base = blockIdx.x * 128;

    {
        const float4* W4 = reinterpret_cast<const float4*>(W);
        float4* ws4 = reinterpret_cast<float4*>(w_s);
        #pragma unroll
        for (int i = tid; i < 1024; i += 128) ws4[i] = W4[i];
    }
    if (tid < 64) b_s[tid] = b[tid];

    for (int f = tid; f < 128 * 16; f += 128) {
        int r = f >> 4, q = f & 15;
        int gr = base + r;
        if (gr >= N_NODES) gr = N_NODES - 1;
        float4 v = reinterpret_cast<const float4*>(x + (size_t)gr * 64)[q];
        float* d = x_s + r * 65 + q * 4;
        d[0] = v.x; d[1] = v.y; d[2] = v.z; d[3] = v.w;
    }
    __syncthreads();

    const int eg = tid >> 3, dg = tid & 7;

    float acc[8][8];
    #pragma unroll
    for (int i = 0; i < 8; i++)
        #pragma unroll
        for (int j = 0; j < 8; j++) acc[i][j] = 0.0f;

    const float4* ws4 = reinterpret_cast<const float4*>(w_s);
    #pragma unroll 4
    for (int c = 0; c < 64; c++) {
        float4 w0 = ws4[c * 16 + dg * 2];
        float4 w1 = ws4[c * 16 + dg * 2 + 1];
        float a[8];
        #pragma unroll
        for (int i = 0; i < 8; i++) a[i] = x_s[(eg * 8 + i) * 65 + c];
        #pragma unroll
        for (int i = 0; i < 8; i++) {
            acc[i][0] += a[i] * w0.x; acc[i][1] += a[i] * w0.y;
            acc[i][2] += a[i] * w0.z; acc[i][3] += a[i] * w0.w;
            acc[i][4] += a[i] * w1.x; acc[i][5] += a[i] * w1.y;
            acc[i][6] += a[i] * w1.z; acc[i][7] += a[i] * w1.w;
        }
    }

    float bb[8];
    #pragma unroll
    for (int j = 0; j < 8; j++) bb[j] = b_s[dg * 8 + j];
    #pragma unroll
    for (int i = 0; i < 8; i++) {
        int n = base + eg * 8 + i;
        if (n < N_NODES) {
            float4 o0 = make_float4(acc[i][0] + bb[0], acc[i][1] + bb[1], acc[i][2] + bb[2], acc[i][3] + bb[3]);
            float4 o1 = make_float4(acc[i][4] + bb[4], acc[i][5] + bb[5], acc[i][6] + bb[6], acc[i][7] + bb[7]);
            float4* dst = reinterpret_cast<float4*>(out + (size_t)n * 64 + dg * 8);
            dst[0] = o0; dst[1] = o1;
        }
    }
}

// ---------------- fused edge kernel: packed f32x2 GEMM + register epilogue ----------------
// Two half-passes (4 dims each) keep regs low; partial score p[i] carried between
// passes; E never touches smem. ea tile stride 66 (u64-aligned rows).
#define EDGE_SMEM_FLOATS (128 * 66 + 4096 + 64 + 256)
__global__ __launch_bounds__(128)
void edge_kernel(const float* __restrict__ ea,
                 const int* __restrict__ eidx,
                 const float* __restrict__ WE, const float* __restrict__ bE,
                 float* __restrict__ out) {
    extern __shared__ float sm[];
    float* ea_s   = sm;                                             // 128*66
    uint64_t* w2  = reinterpret_cast<uint64_t*>(sm + 128 * 66);     // 2048 u64
    float* b_s    = sm + 128 * 66 + 4096;                           // 64
    int* si_s     = reinterpret_cast<int*>(b_s + 64);               // 128
    int* di_s     = si_s + 128;                                     // 128

    const int tid = threadIdx.x;
    const int base = blockIdx.x * 128;

    build_w2(w2, WE, tid);
    if (tid < 64) b_s[tid] = bE[tid];
    si_s[tid] = eidx[base + tid];
    di_s[tid] = eidx[N_EDGES + base + tid];

    // load ea tile, stride 66, float2 stores (rows 8B-aligned)
    for (int f = tid; f < 128 * 16; f += 128) {
        int e = f >> 4, q = f & 15;
        float4 v = reinterpret_cast<const float4*>(ea + (size_t)(base + e) * 64)[q];
        float2* d = reinterpret_cast<float2*>(ea_s + e * 66 + q * 4);
        d[0] = make_float2(v.x, v.y);
        d[1] = make_float2(v.z, v.w);
    }
    __syncthreads();

    const int eg = tid >> 3, dg = tid & 7;
    const uint64_t* arow = reinterpret_cast<const uint64_t*>(ea_s + eg * 8 * 66);

    float p[8];

    #pragma unroll
    for (int h = 0; h < 2; h++) {
        uint64_t acc[8][4];
        #pragma unroll
        for (int i = 0; i < 8; i++)
            #pragma unroll
            for (int j = 0; j < 4; j++) acc[i][j] = 0ull;

        const uint64_t* wp = w2 + h * 32 + dg;

        #pragma unroll 4
        for (int cp = 0; cp < 32; cp++) {
            uint64_t w[4];
            #pragma unroll
            for (int j = 0; j < 4; j++) w[j] = wp[cp * 64 + j * 8];
            uint64_t a[8];
            #pragma unroll
            for (int i = 0; i < 8; i++) a[i] = arow[i * 33 + cp];  // 66 floats = 33 u64
            #pragma unroll
            for (int i = 0; i < 8; i++)
                #pragma unroll
                for (int j = 0; j < 4; j++) fma2(acc[i][j], a[i], w[j]);
        }

        float bb[4];
        #pragma unroll
        for (int j = 0; j < 4; j++) bb[j] = b_s[dg * 8 + h * 4 + j];

        #pragma unroll
        for (int i = 0; i < 8; i++) {
            const int le = eg * 8 + i;
            const int src = si_s[le];
            const int dst = di_s[le];

            float4 k = *reinterpret_cast<const float4*>(g_K + (size_t)src * 64 + dg * 8 + h * 4);
            float4 q = *reinterpret_cast<const float4*>(g_Q + (size_t)dst * 64 + dg * 8 + h * 4);
            float e0 = hsum2(acc[i][0]) + bb[0];
            float e1 = hsum2(acc[i][1]) + bb[1];
            float e2 = hsum2(acc[i][2]) + bb[2];
            float e3 = hsum2(acc[i][3]) + bb[3];
            float t = k.x * q.x * e0 + k.y * q.y * e1 + k.z * q.z * e2 + k.w * q.w * e3;

            if (h == 0) {
                p[i] = t;
            } else {
                float pf = p[i] + t;
                pf += __shfl_xor_sync(0xffffffffu, pf, 1);  // pair = full 16-dim head
                float s = __expf(fminf(fmaxf(pf * 0.25f, -5.0f), 5.0f));

                const float4* Vp = reinterpret_cast<const float4*>(g_V + (size_t)src * 64 + dg * 8);
                float4 v0 = Vp[0], v1 = Vp[1];
                float* ob = out + (size_t)dst * 64 + dg * 8;
                red_add_v4(ob,     v0.x * s, v0.y * s, v0.z * s, v0.w * s);
                red_add_v4(ob + 4, v1.x * s, v1.y * s, v1.z * s, v1.w * s);
                if ((dg & 1) == 0)
                    atomicAdd(g_Z + (size_t)dst * 4 + (dg >> 1), s);
            }
        }
    }
}

// ---------------- finalize ----------------
__global__ void finalize_kernel(float* __restrict__ out) {
    int i = blockIdx.x * blockDim.x + threadIdx.x;
    if (i < N_NODES * HD) {
        int n = i >> 6;
        int h = (i >> 4) & 3;
        out[i] = out[i] / (g_Z[n * 4 + h] + 1e-6f);
    }
}

// ---------------- launch ----------------
extern "C" void kernel_launch(void* const* d_in, const int* in_sizes, int n_in,
                              void* d_out, int out_size) {
    const float* x   = (const float*)d_in[0];
    const float* ea  = (const float*)d_in[1];
    const int*   ei  = (const int*)  d_in[2];
    const float* WQ  = (const float*)d_in[3];
    const float* bQ  = (const float*)d_in[4];
    const float* WK  = (const float*)d_in[5];
    const float* bK  = (const float*)d_in[6];
    const float* WE  = (const float*)d_in[7];
    const float* bE  = (const float*)d_in[8];
    const float* WV  = (const float*)d_in[9];
    const float* bV  = (const float*)d_in[10];
    float* out = (float*)d_out;

    static_assert(EDGE_SMEM_FLOATS * 4 < 227 * 1024, "smem");
    cudaFuncSetAttribute(edge_kernel, cudaFuncAttributeMaxDynamicSharedMemorySize,
                         EDGE_SMEM_FLOATS * (int)sizeof(float));
    cudaFuncSetAttribute(proj_kernel, cudaFuncAttributeMaxDynamicSharedMemorySize,
                         PROJ_SMEM_FLOATS * (int)sizeof(float));

    {
        int total = N_NODES * HD;
        zero_kernel<<<(total + 255) / 256, 256>>>(out);
    }
    {
        dim3 grid((N_NODES + 127) / 128, 3);
        proj_kernel<<<grid, 128, PROJ_SMEM_FLOATS * sizeof(float)>>>(x, WQ, bQ, WK, bK, WV, bV);
    }
    {
        edge_kernel<<<N_EDGES / 128, 128, EDGE_SMEM_FLOATS * sizeof(float)>>>(ea, ei, WE, bE, out);
    }
    {
        int total = N_NODES * HD;
        finalize_kernel<<<(total + 255) / 256, 256>>>(out);
    }
}

// round 6
// speedup vs baseline: 1.1452x; 1.1452x over previous
#include <cuda_runtime.h>
#include <cstdint>

#define N_NODES 50000
#define N_EDGES 1600000
#define IN_DIM 64
#define HD 64
#define NUM_HEADS 4
#define OUT_DIM 16

// ---------------- device scratch ----------------
__device__ float g_Q[N_NODES * HD];
__device__ float g_K[N_NODES * HD];
__device__ float g_V[N_NODES * HD];
__device__ float g_Z[N_NODES * NUM_HEADS];

// ---------------- helpers ----------------
__device__ __forceinline__ void red_add_v4(float* p, float a, float b, float c, float d) {
    asm volatile("red.global.add.v4.f32 [%0], {%1,%2,%3,%4};"
                 :: "l"(p), "f"(a), "f"(b), "f"(c), "f"(d) : "memory");
}
__device__ __forceinline__ uint32_t f2tf32(float f) {
    uint32_t r;
    asm("cvt.rna.tf32.f32 %0, %1;" : "=r"(r) : "f"(f));
    return r;
}
__device__ __forceinline__ void mma_tf32(float d[4], uint32_t a0, uint32_t a1,
                                         uint32_t a2, uint32_t a3,
                                         uint32_t b0, uint32_t b1) {
    asm("mma.sync.aligned.m16n8k8.row.col.f32.tf32.tf32.f32 "
        "{%0,%1,%2,%3}, {%4,%5,%6,%7}, {%8,%9}, {%0,%1,%2,%3};"
        : "+f"(d[0]), "+f"(d[1]), "+f"(d[2]), "+f"(d[3])
        : "r"(a0), "r"(a1), "r"(a2), "r"(a3), "r"(b0), "r"(b1));
}

// ---------------- zero init ----------------
__global__ void zero_kernel(float* __restrict__ out) {
    int i = blockIdx.x * blockDim.x + threadIdx.x;
    if (i < N_NODES * HD) out[i] = 0.0f;
    if (i < N_NODES * NUM_HEADS) g_Z[i] = 0.0f;
}

// ---------------- node projections (R3 scalar, known good) ----------------
#define PROJ_SMEM_FLOATS (128 * 65 + 64 * 64 + 64)
__global__ __launch_bounds__(128)
void proj_kernel(const float* __restrict__ x,
                 const float* __restrict__ WQ, const float* __restrict__ bQ,
                 const float* __restrict__ WK, const float* __restrict__ bK,
                 const float* __restrict__ WV, const float* __restrict__ bV) {
    const float* W; const float* b; float* out;
    if (blockIdx.y == 0)      { W = WQ; b = bQ; out = g_Q; }
    else if (blockIdx.y == 1) { W = WK; b = bK; out = g_K; }
    else                      { W = WV; b = bV; out = g_V; }

    extern __shared__ float sm[];
    float* x_s = sm;
    float* w_s = sm + 128 * 65;
    float* b_s = w_s + 64 * 64;

    const int tid = threadIdx.x;
    const int base = blockIdx.x * 128;

    {
        const float4* W4 = reinterpret_cast<const float4*>(W);
        float4* ws4 = reinterpret_cast<float4*>(w_s);
        #pragma unroll
        for (int i = tid; i < 1024; i += 128) ws4[i] = W4[i];
    }
    if (tid < 64) b_s[tid] = b[tid];

    for (int f = tid; f < 128 * 16; f += 128) {
        int r = f >> 4, q = f & 15;
        int gr = base + r;
        if (gr >= N_NODES) gr = N_NODES - 1;
        float4 v = reinterpret_cast<const float4*>(x + (size_t)gr * 64)[q];
        float* d = x_s + r * 65 + q * 4;
        d[0] = v.x; d[1] = v.y; d[2] = v.z; d[3] = v.w;
    }
    __syncthreads();

    const int eg = tid >> 3, dg = tid & 7;

    float acc[8][8];
    #pragma unroll
    for (int i = 0; i < 8; i++)
        #pragma unroll
        for (int j = 0; j < 8; j++) acc[i][j] = 0.0f;

    const float4* ws4 = reinterpret_cast<const float4*>(w_s);
    #pragma unroll 4
    for (int c = 0; c < 64; c++) {
        float4 w0 = ws4[c * 16 + dg * 2];
        float4 w1 = ws4[c * 16 + dg * 2 + 1];
        float a[8];
        #pragma unroll
        for (int i = 0; i < 8; i++) a[i] = x_s[(eg * 8 + i) * 65 + c];
        #pragma unroll
        for (int i = 0; i < 8; i++) {
            acc[i][0] += a[i] * w0.x; acc[i][1] += a[i] * w0.y;
            acc[i][2] += a[i] * w0.z; acc[i][3] += a[i] * w0.w;
            acc[i][4] += a[i] * w1.x; acc[i][5] += a[i] * w1.y;
            acc[i][6] += a[i] * w1.z; acc[i][7] += a[i] * w1.w;
        }
    }

    float bb[8];
    #pragma unroll
    for (int j = 0; j < 8; j++) bb[j] = b_s[dg * 8 + j];
    #pragma unroll
    for (int i = 0; i < 8; i++) {
        int n = base + eg * 8 + i;
        if (n < N_NODES) {
            float4 o0 = make_float4(acc[i][0] + bb[0], acc[i][1] + bb[1], acc[i][2] + bb[2], acc[i][3] + bb[3]);
            float4 o1 = make_float4(acc[i][4] + bb[4], acc[i][5] + bb[5], acc[i][6] + bb[6], acc[i][7] + bb[7]);
            float4* dst = reinterpret_cast<float4*>(out + (size_t)n * 64 + dg * 8);
            dst[0] = o0; dst[1] = o1;
        }
    }
}

// ---------------- fused edge kernel: tf32 mma.sync GEMM + register epilogue ----------------
// smem float offsets
#define EA_OFF   0            // 128 rows x stride 68 (tf32 bits)
#define EA_STR   68
#define W_OFF    (128 * 68)   // 64 rows(k) x stride 72 (tf32 bits)
#define W_STR    72
#define BIAS_OFF (W_OFF + 64 * 72)        // 64
#define SI_OFF   (BIAS_OFF + 64)          // 128 ints
#define DI_OFF   (SI_OFF + 128)           // 128 ints
#define EDGE_SMEM_FLOATS (DI_OFF + 128)

__global__ __launch_bounds__(128)
void edge_kernel(const float* __restrict__ ea,
                 const int* __restrict__ eidx,
                 const float* __restrict__ WE, const float* __restrict__ bE,
                 float* __restrict__ out) {
    extern __shared__ float sm[];
    uint32_t* ea_s = reinterpret_cast<uint32_t*>(sm + EA_OFF);
    uint32_t* w_s  = reinterpret_cast<uint32_t*>(sm + W_OFF);
    float* bias_s  = sm + BIAS_OFF;
    int* si_s      = reinterpret_cast<int*>(sm + SI_OFF);
    int* di_s      = reinterpret_cast<int*>(sm + DI_OFF);

    const int tid = threadIdx.x;
    const int base = blockIdx.x * 128;

    if (tid < 64) bias_s[tid] = bE[tid];
    si_s[tid] = eidx[base + tid];
    di_s[tid] = eidx[N_EDGES + base + tid];

    // stage A = ea tile (tf32 bits), stride 68
    for (int f = tid; f < 128 * 16; f += 128) {
        int r = f >> 4, q = f & 15;
        float4 v = reinterpret_cast<const float4*>(ea + (size_t)(base + r) * 64)[q];
        uint4 t;
        t.x = f2tf32(v.x); t.y = f2tf32(v.y); t.z = f2tf32(v.z); t.w = f2tf32(v.w);
        *reinterpret_cast<uint4*>(ea_s + r * EA_STR + q * 4) = t;
    }
    // stage B = WE (row-major [k][n]) as tf32 bits, stride 72
    for (int f = tid; f < 64 * 16; f += 128) {
        int k = f >> 4, q = f & 15;
        float4 v = reinterpret_cast<const float4*>(WE + (size_t)k * 64)[q];
        uint4 t;
        t.x = f2tf32(v.x); t.y = f2tf32(v.y); t.z = f2tf32(v.z); t.w = f2tf32(v.w);
        *reinterpret_cast<uint4*>(w_s + k * W_STR + q * 4) = t;
    }
    __syncthreads();

    const int lane = tid & 31;
    const int warp = tid >> 5;
    const int g  = lane >> 2;   // 0..7
    const int tg = lane & 3;    // 0..3
    const int wrow = warp * 32; // this warp's 32 edges

    // ---- Phase A: E = ea @ WE via m16n8k8 tf32 mma ----
    float acc[2][8][4];
    #pragma unroll
    for (int mt = 0; mt < 2; mt++)
        #pragma unroll
        for (int nt = 0; nt < 8; nt++)
            #pragma unroll
            for (int j = 0; j < 4; j++) acc[mt][nt][j] = 0.0f;

    #pragma unroll
    for (int k8 = 0; k8 < 8; k8++) {
        uint32_t a[2][4];
        #pragma unroll
        for (int mt = 0; mt < 2; mt++) {
            int r0 = wrow + mt * 16 + g;
            a[mt][0] = ea_s[(r0)     * EA_STR + k8 * 8 + tg];
            a[mt][1] = ea_s[(r0 + 8) * EA_STR + k8 * 8 + tg];
            a[mt][2] = ea_s[(r0)     * EA_STR + k8 * 8 + tg + 4];
            a[mt][3] = ea_s[(r0 + 8) * EA_STR + k8 * 8 + tg + 4];
        }
        #pragma unroll
        for (int nt = 0; nt < 8; nt++) {
            uint32_t b0 = w_s[(k8 * 8 + tg)     * W_STR + nt * 8 + g];
            uint32_t b1 = w_s[(k8 * 8 + tg + 4) * W_STR + nt * 8 + g];
            mma_tf32(acc[0][nt], a[0][0], a[0][1], a[0][2], a[0][3], b0, b1);
            mma_tf32(acc[1][nt], a[1][0], a[1][1], a[1][2], a[1][3], b0, b1);
        }
    }

    // ---- Phase B: score + scatter ----
    // Thread's acc rows: (mt,rr) -> row = wrow + mt*16 + g + rr*8; cols per nt: nt*8+tg*2, +1.
    #pragma unroll
    for (int mt = 0; mt < 2; mt++) {
        #pragma unroll
        for (int rr = 0; rr < 2; rr++) {
            const int le  = wrow + mt * 16 + g + rr * 8;
            const int src = si_s[le];
            const int dst = di_s[le];
            const float* Kb = g_K + (size_t)src * 64;
            const float* Qb = g_Q + (size_t)dst * 64;

            float part[4] = {0.0f, 0.0f, 0.0f, 0.0f};
            #pragma unroll
            for (int nt = 0; nt < 8; nt++) {
                const int c0 = nt * 8 + tg * 2;
                float2 bb = *reinterpret_cast<const float2*>(bias_s + c0);
                float e0 = acc[mt][nt][rr * 2 + 0] + bb.x;
                float e1 = acc[mt][nt][rr * 2 + 1] + bb.y;
                float2 kk = *reinterpret_cast<const float2*>(Kb + c0);
                float2 qq = *reinterpret_cast<const float2*>(Qb + c0);
                part[nt >> 1] += kk.x * qq.x * e0 + kk.y * qq.y * e1;
            }
            // quad reduce (lanes sharing this row differ only in tg)
            #pragma unroll
            for (int h = 0; h < 4; h++) {
                part[h] += __shfl_xor_sync(0xffffffffu, part[h], 1);
                part[h] += __shfl_xor_sync(0xffffffffu, part[h], 2);
            }
            // lane tg handles head tg
            float s = __expf(fminf(fmaxf(part[tg] * 0.25f, -5.0f), 5.0f));

            const float4* Vp = reinterpret_cast<const float4*>(g_V + (size_t)src * 64 + tg * 16);
            float* ob = out + (size_t)dst * 64 + tg * 16;
            #pragma unroll
            for (int q = 0; q < 4; q++) {
                float4 v = Vp[q];
                red_add_v4(ob + q * 4, v.x * s, v.y * s, v.z * s, v.w * s);
            }
            atomicAdd(g_Z + (size_t)dst * 4 + tg, s);
        }
    }
}

// ---------------- finalize ----------------
__global__ void finalize_kernel(float* __restrict__ out) {
    int i = blockIdx.x * blockDim.x + threadIdx.x;
    if (i < N_NODES * HD) {
        int n = i >> 6;
        int h = (i >> 4) & 3;
        out[i] = out[i] / (g_Z[n * 4 + h] + 1e-6f);
    }
}

// ---------------- launch ----------------
extern "C" void kernel_launch(void* const* d_in, const int* in_sizes, int n_in,
                              void* d_out, int out_size) {
    const float* x   = (const float*)d_in[0];
    const float* ea  = (const float*)d_in[1];
    const int*   ei  = (const int*)  d_in[2];
    const float* WQ  = (const float*)d_in[3];
    const float* bQ  = (const float*)d_in[4];
    const float* WK  = (const float*)d_in[5];
    const float* bK  = (const float*)d_in[6];
    const float* WE  = (const float*)d_in[7];
    const float* bE  = (const float*)d_in[8];
    const float* WV  = (const float*)d_in[9];
    const float* bV  = (const float*)d_in[10];
    float* out = (float*)d_out;

    static_assert(EDGE_SMEM_FLOATS * 4 < 227 * 1024, "smem");
    cudaFuncSetAttribute(edge_kernel, cudaFuncAttributeMaxDynamicSharedMemorySize,
                         EDGE_SMEM_FLOATS * (int)sizeof(float));
    cudaFuncSetAttribute(proj_kernel, cudaFuncAttributeMaxDynamicSharedMemorySize,
                         PROJ_SMEM_FLOATS * (int)sizeof(float));

    {
        int total = N_NODES * HD;
        zero_kernel<<<(total + 255) / 256, 256>>>(out);
    }
    {
        dim3 grid((N_NODES + 127) / 128, 3);
        proj_kernel<<<grid, 128, PROJ_SMEM_FLOATS * sizeof(float)>>>(x, WQ, bQ, WK, bK, WV, bV);
    }
    {
        edge_kernel<<<N_EDGES / 128, 128, EDGE_SMEM_FLOATS * sizeof(float)>>>(ea, ei, WE, bE, out);
    }
    {
        int total = N_NODES * HD;
        finalize_kernel<<<(total + 255) / 256, 256>>>(out);
    }
}

// round 8
// speedup vs baseline: 1.2112x; 1.0577x over previous
#include <cuda_runtime.h>
#include <cstdint>

#define N_NODES 50000
#define N_EDGES 1600000
#define IN_DIM 64
#define HD 64
#define NUM_HEADS 4
#define OUT_DIM 16

// ---------------- device scratch ----------------
__device__ float g_Q[N_NODES * HD];
__device__ float g_K[N_NODES * HD];
__device__ float g_V[N_NODES * HD];
__device__ float g_Z[N_NODES * NUM_HEADS];

// ---------------- helpers ----------------
__device__ __forceinline__ void red_add_v4(float* p, float a, float b, float c, float d) {
    asm volatile("red.global.add.v4.f32 [%0], {%1,%2,%3,%4};"
                 :: "l"(p), "f"(a), "f"(b), "f"(c), "f"(d) : "memory");
}
__device__ __forceinline__ uint32_t f2tf32(float f) {
    uint32_t r;
    asm("cvt.rna.tf32.f32 %0, %1;" : "=r"(r) : "f"(f));
    return r;
}
__device__ __forceinline__ void mma_tf32(float d[4], uint32_t a0, uint32_t a1,
                                         uint32_t a2, uint32_t a3,
                                         uint32_t b0, uint32_t b1) {
    asm("mma.sync.aligned.m16n8k8.row.col.f32.tf32.tf32.f32 "
        "{%0,%1,%2,%3}, {%4,%5,%6,%7}, {%8,%9}, {%0,%1,%2,%3};"
        : "+f"(d[0]), "+f"(d[1]), "+f"(d[2]), "+f"(d[3])
        : "r"(a0), "r"(a1), "r"(a2), "r"(a3), "r"(b0), "r"(b1));
}

// ---------------- zero init ----------------
__global__ void zero_kernel(float* __restrict__ out) {
    int i = blockIdx.x * blockDim.x + threadIdx.x;
    if (i < N_NODES * HD) out[i] = 0.0f;
    if (i < N_NODES * NUM_HEADS) g_Z[i] = 0.0f;
}

// ---------------- node projections (R3 scalar, known good) ----------------
#define PROJ_SMEM_FLOATS (128 * 65 + 64 * 64 + 64)
__global__ __launch_bounds__(128)
void proj_kernel(const float* __restrict__ x,
                 const float* __restrict__ WQ, const float* __restrict__ bQ,
                 const float* __restrict__ WK, const float* __restrict__ bK,
                 const float* __restrict__ WV, const float* __restrict__ bV) {
    const float* W; const float* b; float* out;
    if (blockIdx.y == 0)      { W = WQ; b = bQ; out = g_Q; }
    else if (blockIdx.y == 1) { W = WK; b = bK; out = g_K; }
    else                      { W = WV; b = bV; out = g_V; }

    extern __shared__ float sm[];
    float* x_s = sm;
    float* w_s = sm + 128 * 65;
    float* b_s = w_s + 64 * 64;

    const int tid = threadIdx.x;
    const int base = blockIdx.x * 128;

    {
        const float4* W4 = reinterpret_cast<const float4*>(W);
        float4* ws4 = reinterpret_cast<float4*>(w_s);
        #pragma unroll
        for (int i = tid; i < 1024; i += 128) ws4[i] = W4[i];
    }
    if (tid < 64) b_s[tid] = b[tid];

    for (int f = tid; f < 128 * 16; f += 128) {
        int r = f >> 4, q = f & 15;
        int gr = base + r;
        if (gr >= N_NODES) gr = N_NODES - 1;
        float4 v = reinterpret_cast<const float4*>(x + (size_t)gr * 64)[q];
        float* d = x_s + r * 65 + q * 4;
        d[0] = v.x; d[1] = v.y; d[2] = v.z; d[3] = v.w;
    }
    __syncthreads();

    const int eg = tid >> 3, dg = tid & 7;

    float acc[8][8];
    #pragma unroll
    for (int i = 0; i < 8; i++)
        #pragma unroll
        for (int j = 0; j < 8; j++) acc[i][j] = 0.0f;

    const float4* ws4 = reinterpret_cast<const float4*>(w_s);
    #pragma unroll 4
    for (int c = 0; c < 64; c++) {
        float4 w0 = ws4[c * 16 + dg * 2];
        float4 w1 = ws4[c * 16 + dg * 2 + 1];
        float a[8];
        #pragma unroll
        for (int i = 0; i < 8; i++) a[i] = x_s[(eg * 8 + i) * 65 + c];
        #pragma unroll
        for (int i = 0; i < 8; i++) {
            acc[i][0] += a[i] * w0.x; acc[i][1] += a[i] * w0.y;
            acc[i][2] += a[i] * w0.z; acc[i][3] += a[i] * w0.w;
            acc[i][4] += a[i] * w1.x; acc[i][5] += a[i] * w1.y;
            acc[i][6] += a[i] * w1.z; acc[i][7] += a[i] * w1.w;
        }
    }

    float bb[8];
    #pragma unroll
    for (int j = 0; j < 8; j++) bb[j] = b_s[dg * 8 + j];
    #pragma unroll
    for (int i = 0; i < 8; i++) {
        int n = base + eg * 8 + i;
        if (n < N_NODES) {
            float4 o0 = make_float4(acc[i][0] + bb[0], acc[i][1] + bb[1], acc[i][2] + bb[2], acc[i][3] + bb[3]);
            float4 o1 = make_float4(acc[i][4] + bb[4], acc[i][5] + bb[5], acc[i][6] + bb[6], acc[i][7] + bb[7]);
            float4* dst = reinterpret_cast<float4*>(out + (size_t)n * 64 + dg * 8);
            dst[0] = o0; dst[1] = o1;
        }
    }
}

// ---------------- fused edge kernel: tf32 mma GEMM -> E in smem -> float4 epilogue ----
#define EA_OFF   0            // 128 rows x stride 68 (tf32 bits in, fp32 E out)
#define EA_STR   68
#define W_OFF    (128 * 68)   // 64 rows(k) x stride 72 (R6-correct layout)
#define W_STR    72
#define BIAS_OFF (W_OFF + 64 * 72)        // 64
#define SI_OFF   (BIAS_OFF + 64)          // 128 ints
#define DI_OFF   (SI_OFF + 128)           // 128 ints
#define EDGE_SMEM_FLOATS (DI_OFF + 128)

__global__ __launch_bounds__(128)
void edge_kernel(const float* __restrict__ ea,
                 const int* __restrict__ eidx,
                 const float* __restrict__ WE, const float* __restrict__ bE,
                 float* __restrict__ out) {
    extern __shared__ float sm[];
    uint32_t* ea_s = reinterpret_cast<uint32_t*>(sm + EA_OFF);
    float* E_s     = sm + EA_OFF;               // reused after MMA
    uint32_t* w_s  = reinterpret_cast<uint32_t*>(sm + W_OFF);
    float* bias_s  = sm + BIAS_OFF;
    int* si_s      = reinterpret_cast<int*>(sm + SI_OFF);
    int* di_s      = reinterpret_cast<int*>(sm + DI_OFF);

    const int tid = threadIdx.x;
    const int base = blockIdx.x * 128;

    if (tid < 64) bias_s[tid] = bE[tid];
    si_s[tid] = eidx[base + tid];
    di_s[tid] = eidx[N_EDGES + base + tid];

    // stage A = ea tile (tf32 bits), stride 68
    for (int f = tid; f < 128 * 16; f += 128) {
        int r = f >> 4, q = f & 15;
        float4 v = reinterpret_cast<const float4*>(ea + (size_t)(base + r) * 64)[q];
        uint4 t;
        t.x = f2tf32(v.x); t.y = f2tf32(v.y); t.z = f2tf32(v.z); t.w = f2tf32(v.w);
        *reinterpret_cast<uint4*>(ea_s + r * EA_STR + q * 4) = t;
    }
    // stage B = WE (row-major [k][n]) as tf32 bits, stride 72 (R6-correct)
    for (int f = tid; f < 64 * 16; f += 128) {
        int k = f >> 4, q = f & 15;
        float4 v = reinterpret_cast<const float4*>(WE + (size_t)k * 64)[q];
        uint4 t;
        t.x = f2tf32(v.x); t.y = f2tf32(v.y); t.z = f2tf32(v.z); t.w = f2tf32(v.w);
        *reinterpret_cast<uint4*>(w_s + k * W_STR + q * 4) = t;
    }
    __syncthreads();

    const int lane = tid & 31;
    const int warp = tid >> 5;
    const int g  = lane >> 2;   // 0..7
    const int tg = lane & 3;    // 0..3
    const int wrow = warp * 32; // this warp's 32 edges

    // ---- Phase A: E = ea @ WE via m16n8k8 tf32 mma (R6-verified mapping) ----
    float acc[2][8][4];
    #pragma unroll
    for (int mt = 0; mt < 2; mt++)
        #pragma unroll
        for (int nt = 0; nt < 8; nt++)
            #pragma unroll
            for (int j = 0; j < 4; j++) acc[mt][nt][j] = 0.0f;

    #pragma unroll
    for (int k8 = 0; k8 < 8; k8++) {
        uint32_t a[2][4];
        #pragma unroll
        for (int mt = 0; mt < 2; mt++) {
            int r0 = wrow + mt * 16 + g;
            a[mt][0] = ea_s[(r0)     * EA_STR + k8 * 8 + tg];
            a[mt][1] = ea_s[(r0 + 8) * EA_STR + k8 * 8 + tg];
            a[mt][2] = ea_s[(r0)     * EA_STR + k8 * 8 + tg + 4];
            a[mt][3] = ea_s[(r0 + 8) * EA_STR + k8 * 8 + tg + 4];
        }
        #pragma unroll
        for (int nt = 0; nt < 8; nt++) {
            uint32_t b0 = w_s[(k8 * 8 + tg)     * W_STR + nt * 8 + g];
            uint32_t b1 = w_s[(k8 * 8 + tg + 4) * W_STR + nt * 8 + g];
            mma_tf32(acc[0][nt], a[0][0], a[0][1], a[0][2], a[0][3], b0, b1);
            mma_tf32(acc[1][nt], a[1][0], a[1][1], a[1][2], a[1][3], b0, b1);
        }
    }

    // ---- store E (+bias) back into this warp's own rows of ea_s (no sync needed:
    //      each warp reads/writes only rows wrow..wrow+31) ----
    #pragma unroll
    for (int mt = 0; mt < 2; mt++) {
        #pragma unroll
        for (int rr = 0; rr < 2; rr++) {
            const int row = wrow + mt * 16 + rr * 8 + g;
            #pragma unroll
            for (int nt = 0; nt < 8; nt++) {
                const int c0 = nt * 8 + tg * 2;
                float2 bb = *reinterpret_cast<const float2*>(bias_s + c0);
                *reinterpret_cast<float2*>(E_s + row * EA_STR + c0) =
                    make_float2(acc[mt][nt][rr * 2 + 0] + bb.x,
                                acc[mt][nt][rr * 2 + 1] + bb.y);
            }
        }
    }
    __syncthreads();

    // ---- Phase B: per (edge, head): score + scatter, all float4 ----
    #pragma unroll
    for (int pass = 0; pass < 4; pass++) {
        const int le = pass * 32 + (tid >> 2);
        const int h  = tid & 3;
        const int src = si_s[le];
        const int dst = di_s[le];

        const float4* Kp = reinterpret_cast<const float4*>(g_K + (size_t)src * 64 + h * 16);
        const float4* Qp = reinterpret_cast<const float4*>(g_Q + (size_t)dst * 64 + h * 16);
        const float4* Ep = reinterpret_cast<const float4*>(E_s + le * EA_STR + h * 16);

        float p = 0.0f;
        #pragma unroll
        for (int q = 0; q < 4; q++) {
            float4 k = Kp[q];
            float4 qv = Qp[q];
            float4 e = Ep[q];
            p += k.x * qv.x * e.x + k.y * qv.y * e.y + k.z * qv.z * e.z + k.w * qv.w * e.w;
        }
        float s = __expf(fminf(fmaxf(p * 0.25f, -5.0f), 5.0f));

        const float4* Vp = reinterpret_cast<const float4*>(g_V + (size_t)src * 64 + h * 16);
        float* ob = out + (size_t)dst * 64 + h * 16;
        #pragma unroll
        for (int q = 0; q < 4; q++) {
            float4 v = Vp[q];
            red_add_v4(ob + q * 4, v.x * s, v.y * s, v.z * s, v.w * s);
        }
        // Z: one red.v4 per edge (gather the quad's 4 head scores to h==0 lane)
        const int qbase = (tid & 31) & ~3;
        float s0 = __shfl_sync(0xffffffffu, s, qbase);
        float s1 = __shfl_sync(0xffffffffu, s, qbase + 1);
        float s2 = __shfl_sync(0xffffffffu, s, qbase + 2);
        float s3 = __shfl_sync(0xffffffffu, s, qbase + 3);
        if (h == 0)
            red_add_v4(g_Z + (size_t)dst * 4, s0, s1, s2, s3);
    }
}

// ---------------- finalize ----------------
__global__ void finalize_kernel(float* __restrict__ out) {
    int i = blockIdx.x * blockDim.x + threadIdx.x;
    if (i < N_NODES * HD) {
        int n = i >> 6;
        int h = (i >> 4) & 3;
        out[i] = out[i] / (g_Z[n * 4 + h] + 1e-6f);
    }
}

// ---------------- launch ----------------
extern "C" void kernel_launch(void* const* d_in, const int* in_sizes, int n_in,
                              void* d_out, int out_size) {
    const float* x   = (const float*)d_in[0];
    const float* ea  = (const float*)d_in[1];
    const int*   ei  = (const int*)  d_in[2];
    const float* WQ  = (const float*)d_in[3];
    const float* bQ  = (const float*)d_in[4];
    const float* WK  = (const float*)d_in[5];
    const float* bK  = (const float*)d_in[6];
    const float* WE  = (const float*)d_in[7];
    const float* bE  = (const float*)d_in[8];
    const float* WV  = (const float*)d_in[9];
    const float* bV  = (const float*)d_in[10];
    float* out = (float*)d_out;

    static_assert(EDGE_SMEM_FLOATS * 4 < 227 * 1024, "smem");
    cudaFuncSetAttribute(edge_kernel, cudaFuncAttributeMaxDynamicSharedMemorySize,
                         EDGE_SMEM_FLOATS * (int)sizeof(float));
    cudaFuncSetAttribute(proj_kernel, cudaFuncAttributeMaxDynamicSharedMemorySize,
                         PROJ_SMEM_FLOATS * (int)sizeof(float));

    {
        int total = N_NODES * HD;
        zero_kernel<<<(total + 255) / 256, 256>>>(out);
    }
    {
        dim3 grid((N_NODES + 127) / 128, 3);
        proj_kernel<<<grid, 128, PROJ_SMEM_FLOATS * sizeof(float)>>>(x, WQ, bQ, WK, bK, WV, bV);
    }
    {
        edge_kernel<<<N_EDGES / 128, 128, EDGE_SMEM_FLOATS * sizeof(float)>>>(ea, ei, WE, bE, out);
    }
    {
        int total = N_NODES * HD;
        finalize_kernel<<<(total + 255) / 256, 256>>>(out);
    }
}

// round 9
// speedup vs baseline: 1.3159x; 1.0864x over previous
#include <cuda_runtime.h>
#include <cstdint>

#define N_NODES 50000
#define N_EDGES 1600000
#define IN_DIM 64
#define HD 64
#define NUM_HEADS 4
#define OUT_DIM 16

// ---------------- device scratch ----------------
__device__ float g_Q[N_NODES * HD];
__device__ float g_K[N_NODES * HD];
__device__ float g_V[N_NODES * HD];
__device__ float g_Z[N_NODES * NUM_HEADS];

// ---------------- helpers ----------------
__device__ __forceinline__ void red_add_v4(float* p, float a, float b, float c, float d) {
    asm volatile("red.global.add.v4.f32 [%0], {%1,%2,%3,%4};"
                 :: "l"(p), "f"(a), "f"(b), "f"(c), "f"(d) : "memory");
}
__device__ __forceinline__ uint32_t f2tf32(float f) {
    uint32_t r;
    asm("cvt.rna.tf32.f32 %0, %1;" : "=r"(r) : "f"(f));
    return r;
}
__device__ __forceinline__ void mma_tf32(float d[4], uint32_t a0, uint32_t a1,
                                         uint32_t a2, uint32_t a3,
                                         uint32_t b0, uint32_t b1) {
    asm("mma.sync.aligned.m16n8k8.row.col.f32.tf32.tf32.f32 "
        "{%0,%1,%2,%3}, {%4,%5,%6,%7}, {%8,%9}, {%0,%1,%2,%3};"
        : "+f"(d[0]), "+f"(d[1]), "+f"(d[2]), "+f"(d[3])
        : "r"(a0), "r"(a1), "r"(a2), "r"(a3), "r"(b0), "r"(b1));
}

// ---------------- zero init ----------------
__global__ void zero_kernel(float* __restrict__ out) {
    int i = blockIdx.x * blockDim.x + threadIdx.x;
    if (i < N_NODES * HD) out[i] = 0.0f;
    if (i < N_NODES * NUM_HEADS) g_Z[i] = 0.0f;
}

// ---------------- node projections (R3 scalar, known good) ----------------
#define PROJ_SMEM_FLOATS (128 * 65 + 64 * 64 + 64)
__global__ __launch_bounds__(128)
void proj_kernel(const float* __restrict__ x,
                 const float* __restrict__ WQ, const float* __restrict__ bQ,
                 const float* __restrict__ WK, const float* __restrict__ bK,
                 const float* __restrict__ WV, const float* __restrict__ bV) {
    const float* W; const float* b; float* out;
    if (blockIdx.y == 0)      { W = WQ; b = bQ; out = g_Q; }
    else if (blockIdx.y == 1) { W = WK; b = bK; out = g_K; }
    else                      { W = WV; b = bV; out = g_V; }

    extern __shared__ float sm[];
    float* x_s = sm;
    float* w_s = sm + 128 * 65;
    float* b_s = w_s + 64 * 64;

    const int tid = threadIdx.x;
    const int base = blockIdx.x * 128;

    {
        const float4* W4 = reinterpret_cast<const float4*>(W);
        float4* ws4 = reinterpret_cast<float4*>(w_s);
        #pragma unroll
        for (int i = tid; i < 1024; i += 128) ws4[i] = W4[i];
    }
    if (tid < 64) b_s[tid] = b[tid];

    for (int f = tid; f < 128 * 16; f += 128) {
        int r = f >> 4, q = f & 15;
        int gr = base + r;
        if (gr >= N_NODES) gr = N_NODES - 1;
        float4 v = reinterpret_cast<const float4*>(x + (size_t)gr * 64)[q];
        float* d = x_s + r * 65 + q * 4;
        d[0] = v.x; d[1] = v.y; d[2] = v.z; d[3] = v.w;
    }
    __syncthreads();

    const int eg = tid >> 3, dg = tid & 7;

    float acc[8][8];
    #pragma unroll
    for (int i = 0; i < 8; i++)
        #pragma unroll
        for (int j = 0; j < 8; j++) acc[i][j] = 0.0f;

    const float4* ws4 = reinterpret_cast<const float4*>(w_s);
    #pragma unroll 4
    for (int c = 0; c < 64; c++) {
        float4 w0 = ws4[c * 16 + dg * 2];
        float4 w1 = ws4[c * 16 + dg * 2 + 1];
        float a[8];
        #pragma unroll
        for (int i = 0; i < 8; i++) a[i] = x_s[(eg * 8 + i) * 65 + c];
        #pragma unroll
        for (int i = 0; i < 8; i++) {
            acc[i][0] += a[i] * w0.x; acc[i][1] += a[i] * w0.y;
            acc[i][2] += a[i] * w0.z; acc[i][3] += a[i] * w0.w;
            acc[i][4] += a[i] * w1.x; acc[i][5] += a[i] * w1.y;
            acc[i][6] += a[i] * w1.z; acc[i][7] += a[i] * w1.w;
        }
    }

    float bb[8];
    #pragma unroll
    for (int j = 0; j < 8; j++) bb[j] = b_s[dg * 8 + j];
    #pragma unroll
    for (int i = 0; i < 8; i++) {
        int n = base + eg * 8 + i;
        if (n < N_NODES) {
            float4 o0 = make_float4(acc[i][0] + bb[0], acc[i][1] + bb[1], acc[i][2] + bb[2], acc[i][3] + bb[3]);
            float4 o1 = make_float4(acc[i][4] + bb[4], acc[i][5] + bb[5], acc[i][6] + bb[6], acc[i][7] + bb[7]);
            float4* dst = reinterpret_cast<float4*>(out + (size_t)n * 64 + dg * 8);
            dst[0] = o0; dst[1] = o1;
        }
    }
}

// ---------------- fused edge kernel: 64-edge tiles, tf32 mma + float4 epilogue ----
// smem 36.6KB -> 5 blocks/SM (launch_bounds), 20 warps/SM for latency hiding.
#define TILE_E   64
#define EA_OFF   0            // 64 rows x stride 68
#define EA_STR   68
#define W_OFF    (TILE_E * 68)   // 64 rows(k) x stride 72
#define W_STR    72
#define BIAS_OFF (W_OFF + 64 * 72)        // 64
#define SI_OFF   (BIAS_OFF + 64)          // 64 ints
#define DI_OFF   (SI_OFF + TILE_E)        // 64 ints
#define EDGE_SMEM_FLOATS (DI_OFF + TILE_E)

__global__ __launch_bounds__(128, 5)
void edge_kernel(const float* __restrict__ ea,
                 const int* __restrict__ eidx,
                 const float* __restrict__ WE, const float* __restrict__ bE,
                 float* __restrict__ out) {
    extern __shared__ float sm[];
    uint32_t* ea_s = reinterpret_cast<uint32_t*>(sm + EA_OFF);
    float* E_s     = sm + EA_OFF;               // reused after MMA
    uint32_t* w_s  = reinterpret_cast<uint32_t*>(sm + W_OFF);
    float* bias_s  = sm + BIAS_OFF;
    int* si_s      = reinterpret_cast<int*>(sm + SI_OFF);
    int* di_s      = reinterpret_cast<int*>(sm + DI_OFF);

    const int tid = threadIdx.x;
    const int base = blockIdx.x * TILE_E;

    if (tid < 64) bias_s[tid] = bE[tid];
    if (tid < TILE_E) {
        si_s[tid] = eidx[base + tid];
        di_s[tid] = eidx[N_EDGES + base + tid];
    }

    // stage A = ea tile (tf32 bits), stride 68 : 64 rows x 16 float4 = 1024 / 128 thr = 8
    for (int f = tid; f < TILE_E * 16; f += 128) {
        int r = f >> 4, q = f & 15;
        float4 v = reinterpret_cast<const float4*>(ea + (size_t)(base + r) * 64)[q];
        uint4 t;
        t.x = f2tf32(v.x); t.y = f2tf32(v.y); t.z = f2tf32(v.z); t.w = f2tf32(v.w);
        *reinterpret_cast<uint4*>(ea_s + r * EA_STR + q * 4) = t;
    }
    // stage B = WE (row-major [k][n]) as tf32 bits, stride 72
    for (int f = tid; f < 64 * 16; f += 128) {
        int k = f >> 4, q = f & 15;
        float4 v = reinterpret_cast<const float4*>(WE + (size_t)k * 64)[q];
        uint4 t;
        t.x = f2tf32(v.x); t.y = f2tf32(v.y); t.z = f2tf32(v.z); t.w = f2tf32(v.w);
        *reinterpret_cast<uint4*>(w_s + k * W_STR + q * 4) = t;
    }
    __syncthreads();

    const int lane = tid & 31;
    const int warp = tid >> 5;
    const int g  = lane >> 2;   // 0..7
    const int tg = lane & 3;    // 0..3
    const int wrow = warp * 16; // this warp's 16 edges

    // ---- Phase A: E = ea @ WE via m16n8k8 tf32 mma (one m-tile per warp) ----
    float acc[8][4];
    #pragma unroll
    for (int nt = 0; nt < 8; nt++)
        #pragma unroll
        for (int j = 0; j < 4; j++) acc[nt][j] = 0.0f;

    #pragma unroll
    for (int k8 = 0; k8 < 8; k8++) {
        const int r0 = wrow + g;
        uint32_t a0 = ea_s[(r0)     * EA_STR + k8 * 8 + tg];
        uint32_t a1 = ea_s[(r0 + 8) * EA_STR + k8 * 8 + tg];
        uint32_t a2 = ea_s[(r0)     * EA_STR + k8 * 8 + tg + 4];
        uint32_t a3 = ea_s[(r0 + 8) * EA_STR + k8 * 8 + tg + 4];
        #pragma unroll
        for (int nt = 0; nt < 8; nt++) {
            uint32_t b0 = w_s[(k8 * 8 + tg)     * W_STR + nt * 8 + g];
            uint32_t b1 = w_s[(k8 * 8 + tg + 4) * W_STR + nt * 8 + g];
            mma_tf32(acc[nt], a0, a1, a2, a3, b0, b1);
        }
    }

    // ---- store E (+bias) into this warp's own rows (no sync needed) ----
    #pragma unroll
    for (int rr = 0; rr < 2; rr++) {
        const int row = wrow + rr * 8 + g;
        #pragma unroll
        for (int nt = 0; nt < 8; nt++) {
            const int c0 = nt * 8 + tg * 2;
            float2 bb = *reinterpret_cast<const float2*>(bias_s + c0);
            *reinterpret_cast<float2*>(E_s + row * EA_STR + c0) =
                make_float2(acc[nt][rr * 2 + 0] + bb.x,
                            acc[nt][rr * 2 + 1] + bb.y);
        }
    }
    __syncthreads();

    // ---- Phase B: per (edge, head): score + scatter, all float4 ----
    #pragma unroll
    for (int pass = 0; pass < 2; pass++) {
        const int le = pass * 32 + (tid >> 2);
        const int h  = tid & 3;
        const int src = si_s[le];
        const int dst = di_s[le];

        const float4* Kp = reinterpret_cast<const float4*>(g_K + (size_t)src * 64 + h * 16);
        const float4* Qp = reinterpret_cast<const float4*>(g_Q + (size_t)dst * 64 + h * 16);
        const float4* Ep = reinterpret_cast<const float4*>(E_s + le * EA_STR + h * 16);

        float p = 0.0f;
        #pragma unroll
        for (int q = 0; q < 4; q++) {
            float4 k = Kp[q];
            float4 qv = Qp[q];
            float4 e = Ep[q];
            p += k.x * qv.x * e.x + k.y * qv.y * e.y + k.z * qv.z * e.z + k.w * qv.w * e.w;
        }
        float s = __expf(fminf(fmaxf(p * 0.25f, -5.0f), 5.0f));

        const float4* Vp = reinterpret_cast<const float4*>(g_V + (size_t)src * 64 + h * 16);
        float* ob = out + (size_t)dst * 64 + h * 16;
        #pragma unroll
        for (int q = 0; q < 4; q++) {
            float4 v = Vp[q];
            red_add_v4(ob + q * 4, v.x * s, v.y * s, v.z * s, v.w * s);
        }
        // Z: one red.v4 per edge (gather the quad's 4 head scores to h==0 lane)
        const int qbase = (tid & 31) & ~3;
        float s0 = __shfl_sync(0xffffffffu, s, qbase);
        float s1 = __shfl_sync(0xffffffffu, s, qbase + 1);
        float s2 = __shfl_sync(0xffffffffu, s, qbase + 2);
        float s3 = __shfl_sync(0xffffffffu, s, qbase + 3);
        if (h == 0)
            red_add_v4(g_Z + (size_t)dst * 4, s0, s1, s2, s3);
    }
}

// ---------------- finalize ----------------
__global__ void finalize_kernel(float* __restrict__ out) {
    int i = blockIdx.x * blockDim.x + threadIdx.x;
    if (i < N_NODES * HD) {
        int n = i >> 6;
        int h = (i >> 4) & 3;
        out[i] = out[i] / (g_Z[n * 4 + h] + 1e-6f);
    }
}

// ---------------- launch ----------------
extern "C" void kernel_launch(void* const* d_in, const int* in_sizes, int n_in,
                              void* d_out, int out_size) {
    const float* x   = (const float*)d_in[0];
    const float* ea  = (const float*)d_in[1];
    const int*   ei  = (const int*)  d_in[2];
    const float* WQ  = (const float*)d_in[3];
    const float* bQ  = (const float*)d_in[4];
    const float* WK  = (const float*)d_in[5];
    const float* bK  = (const float*)d_in[6];
    const float* WE  = (const float*)d_in[7];
    const float* bE  = (const float*)d_in[8];
    const float* WV  = (const float*)d_in[9];
    const float* bV  = (const float*)d_in[10];
    float* out = (float*)d_out;

    static_assert(EDGE_SMEM_FLOATS * 4 * 5 < 227 * 1024, "smem occupancy");
    cudaFuncSetAttribute(edge_kernel, cudaFuncAttributeMaxDynamicSharedMemorySize,
                         EDGE_SMEM_FLOATS * (int)sizeof(float));
    cudaFuncSetAttribute(proj_kernel, cudaFuncAttributeMaxDynamicSharedMemorySize,
                         PROJ_SMEM_FLOATS * (int)sizeof(float));

    {
        int total = N_NODES * HD;
        zero_kernel<<<(total + 255) / 256, 256>>>(out);
    }
    {
        dim3 grid((N_NODES + 127) / 128, 3);
        proj_kernel<<<grid, 128, PROJ_SMEM_FLOATS * sizeof(float)>>>(x, WQ, bQ, WK, bK, WV, bV);
    }
    {
        edge_kernel<<<N_EDGES / TILE_E, 128, EDGE_SMEM_FLOATS * sizeof(float)>>>(ea, ei, WE, bE, out);
    }
    {
        int total = N_NODES * HD;
        finalize_kernel<<<(total + 255) / 256, 256>>>(out);
    }
}